// round 9
// baseline (speedup 1.0000x reference)
#include <cuda_runtime.h>
#include <math.h>

#define FULL_MASK 0xffffffffu
typedef unsigned long long ull;

// ---- f32x2 packed-math helpers ----
__device__ __forceinline__ ull pk2(float lo, float hi) {
    ull r; asm("mov.b64 %0,{%1,%2};" : "=l"(r) : "f"(lo), "f"(hi)); return r;
}
__device__ __forceinline__ void up2(ull v, float& lo, float& hi) {
    asm("mov.b64 {%0,%1},%2;" : "=f"(lo), "=f"(hi) : "l"(v));
}
__device__ __forceinline__ ull fma2(ull a, ull b, ull c) {
    ull d; asm("fma.rn.f32x2 %0,%1,%2,%3;" : "=l"(d) : "l"(a), "l"(b), "l"(c)); return d;
}
__device__ __forceinline__ ull mul2(ull a, ull b) {
    ull d; asm("mul.rn.f32x2 %0,%1,%2;" : "=l"(d) : "l"(a), "l"(b)); return d;
}
__device__ __forceinline__ float tanh_hw(float x) {
    float y; asm("tanh.approx.f32 %0, %1;" : "=f"(y) : "f"(x)); return y;
}

// Forward-Euler ScaledODENet, one warp per batch element (32 CTAs x 32 thr).
//
// Allreduce via integer REDUX (one instruction per output, sum lands in
// every lane): W2 is pre-scaled by S/sr (S = power of 2 picked from the
// actual weights so per-lane terms fit 2^25 -> 32-lane s32 sums < 2^30).
//   a    = U + x*w0 ; h = tanh(a)
//   v[j] = h_lo*W2s[l][j] + h_hi*W2s[l+32][j]       (packed fma2)
//   iv   = __float2int_rn(v)                        (exact-range fixed point)
//   ds   = __reduce_add_sync(iv)  -> (float)        (d * S, all lanes)
//   U   += sum_j ds_j * (W1col_j / S) + c           (scalar 4-wide trees)
//   ys0 += ds_0/S + b2[0]/sr                        (lane 0 stores out)
// No shuffle reduction, no broadcast, no smem, no syncwarp.
__global__ __launch_bounds__(32, 1)
void ode_fe_kernel(const float* __restrict__ x,
                   const float* __restrict__ W1,
                   const float* __restrict__ b1,
                   const float* __restrict__ b2,
                   const float* __restrict__ W2,
                   float* __restrict__ out,
                   int T) {
    constexpr int B = 32;
    const int b = blockIdx.x;
    const int l = threadIdx.x;              // owns hidden units l, l+32
    const float inv_sr = 1.0f / 44100.0f;

    // ---- runtime fixed-point scale from actual weight magnitudes ----
    // per-lane, per-output term bound: |v| <= (|W2[l][j]| + |W2[l+32][j]|)/sr
    float tb = 1e-30f;
#pragma unroll
    for (int j = 0; j < 16; ++j)
        tb = fmaxf(tb, (fabsf(W2[l * 16 + j]) + fabsf(W2[(l + 32) * 16 + j])) * inv_sr);
#pragma unroll
    for (int off = 16; off > 0; off >>= 1)
        tb = fmaxf(tb, __shfl_xor_sync(FULL_MASK, tb, off));
    int e;
    frexpf(tb, &e);                          // tb < 2^e
    const float S    = ldexpf(1.0f, 25 - e); // tb * S < 2^25
    const float invS = ldexpf(1.0f, e - 25); // exact (powers of two)

    // ---- one-time weight staging ----
    const ull w02 = pk2(W1[l], W1[l + 32]);           // W1 row 0 (x weights)

    // W2 rows l, l+32 scaled by S/sr, packed over output pairs (2m, 2m+1)
    const float Ssr = S * inv_sr;
    ull w2A[8], w2B[8];
#pragma unroll
    for (int m = 0; m < 8; ++m) {
        w2A[m] = pk2(W2[l * 16 + 2 * m] * Ssr,        W2[l * 16 + 2 * m + 1] * Ssr);
        w2B[m] = pk2(W2[(l + 32) * 16 + 2 * m] * Ssr, W2[(l + 32) * 16 + 2 * m + 1] * Ssr);
    }

    // W1 state columns divided by S (consumes the fixed-point scale for free)
    float w1lo[16], w1hi[16];
#pragma unroll
    for (int j = 0; j < 16; ++j) {
        w1lo[j] = W1[(j + 1) * 64 + l]      * invS;
        w1hi[j] = W1[(j + 1) * 64 + l + 32] * invS;
    }

    // c = W1s^T (b2/sr) per owned unit (unscaled; seeds the trees)
    float clo = 0.0f, chi = 0.0f;
#pragma unroll
    for (int j = 0; j < 16; ++j) {
        const float bj = b2[j] * inv_sr;
        clo = fmaf(bj, W1[(j + 1) * 64 + l],      clo);
        chi = fmaf(bj, W1[(j + 1) * 64 + l + 32], chi);
    }
    const float b20s = b2[0] * inv_sr;

    // ---- loop-carried state ----
    ull U2 = pk2(b1[l], b1[l + 32]);        // U = b1 + W1s^T ys (ys starts 0)
    float ys0 = 0.0f;

    if (l == 0) out[b] = 0.0f;              // t=0 output row is zeros
    const int nsteps = T - 1;

    // x prefetch: 32 timesteps per register, one block ahead
    float xbuf  = (l < nsteps)      ? x[l * B + b]        : 0.0f;
    float xnext = (l + 32 < nsteps) ? x[(l + 32) * B + b] : 0.0f;
    float xt = __shfl_sync(FULL_MASK, xbuf, 0);

#pragma unroll 1
    for (int t = 0; t < nsteps; ++t) {
        // ---- a = U + x*w0 ; h = tanh(a) ----
        const ull a2 = fma2(pk2(xt, xt), w02, U2);
        float alo, ahi;
        up2(a2, alo, ahi);
        const float hlo = tanh_hw(alo);
        const float hhi = tanh_hw(ahi);

        // ---- packed per-lane W2 partials (natural slot order) ----
        const ull h2lo = pk2(hlo, hlo);
        const ull h2hi = pk2(hhi, hhi);
        float v[16];
#pragma unroll
        for (int m = 0; m < 8; ++m) {
            const ull p2 = fma2(h2lo, w2A[m], mul2(h2hi, w2B[m]));
            up2(p2, v[2 * m], v[2 * m + 1]);
        }

        // ---- fixed-point convert + hardware s32 warp allreduce ----
        float d[16];
#pragma unroll
        for (int j = 0; j < 16; ++j) {
            const int iv = __float2int_rn(v[j]);
            d[j] = (float)__reduce_add_sync(FULL_MASK, iv);   // = true_d * S
        }

        // ---- output channel (off the critical chain) ----
        ys0 += fmaf(d[0], invS, b20s);
        if (l == 0) out[(t + 1) * B + b] = ys0;

        // refill / prefetch next xt (independent of U update)
        if ((t & 31) == 31) {
            xbuf = xnext;
            const int tn = t + 33 + l;
            xnext = (tn < nsteps) ? x[tn * B + b] : 0.0f;
        }
        xt = __shfl_sync(FULL_MASK, xbuf, (t + 1) & 31);

        // ---- U += sum_j d_j * (W1col_j/S) + c  (scalar 4-wide trees) ----
        float s0 = fmaf(d[0],  w1lo[0],  clo);
        float s1 = d[4]  * w1lo[4];
        float s2 = d[8]  * w1lo[8];
        float s3 = d[12] * w1lo[12];
        float r0 = fmaf(d[0],  w1hi[0],  chi);
        float r1 = d[4]  * w1hi[4];
        float r2 = d[8]  * w1hi[8];
        float r3 = d[12] * w1hi[12];
#pragma unroll
        for (int j = 1; j < 4; ++j) {
            s0 = fmaf(d[j],      w1lo[j],      s0);
            s1 = fmaf(d[j + 4],  w1lo[j + 4],  s1);
            s2 = fmaf(d[j + 8],  w1lo[j + 8],  s2);
            s3 = fmaf(d[j + 12], w1lo[j + 12], s3);
            r0 = fmaf(d[j],      w1hi[j],      r0);
            r1 = fmaf(d[j + 4],  w1hi[j + 4],  r1);
            r2 = fmaf(d[j + 8],  w1hi[j + 8],  r2);
            r3 = fmaf(d[j + 12], w1hi[j + 12], r3);
        }
        const float dUlo = (s0 + s1) + (s2 + s3);
        const float dUhi = (r0 + r1) + (r2 + r3);
        float Ulo, Uhi;
        up2(U2, Ulo, Uhi);
        U2 = pk2(Ulo + dUlo, Uhi + dUhi);
    }
}

extern "C" void kernel_launch(void* const* d_in, const int* in_sizes, int n_in,
                              void* d_out, int out_size) {
    const float* x  = (const float*)d_in[0];
    const float* W1 = (const float*)d_in[1];
    const float* b1 = (const float*)d_in[2];
    const float* W2 = (const float*)d_in[3];
    const float* b2 = (const float*)d_in[4];
    float* out = (float*)d_out;

    const int T = in_sizes[0] / 32;   // x is (T, B=32, F=1)
    ode_fe_kernel<<<32, 32>>>(x, W1, b1, b2, W2, out, T);
}

// round 10
// speedup vs baseline: 2.8986x; 2.8986x over previous
#include <cuda_runtime.h>
#include <math.h>

#define FULL_MASK 0xffffffffu
typedef unsigned long long ull;

// ---- f32x2 packed-math helpers ----
__device__ __forceinline__ ull pk2(float lo, float hi) {
    ull r; asm("mov.b64 %0,{%1,%2};" : "=l"(r) : "f"(lo), "f"(hi)); return r;
}
__device__ __forceinline__ void up2(ull v, float& lo, float& hi) {
    asm("mov.b64 {%0,%1},%2;" : "=f"(lo), "=f"(hi) : "l"(v));
}
__device__ __forceinline__ ull fma2(ull a, ull b, ull c) {
    ull d; asm("fma.rn.f32x2 %0,%1,%2,%3;" : "=l"(d) : "l"(a), "l"(b), "l"(c)); return d;
}
__device__ __forceinline__ float tanh_hw(float x) {
    float y; asm("tanh.approx.f32 %0, %1;" : "=f"(y) : "f"(x)); return y;
}

#define KBLK 1024      // timesteps per block (2 per thread, 512 threads)
#define NSWEEP 3       // Picard sweeps; error ~ (lambda*K)^m, lambda*K ~ 0.0074

// Parallel-in-time forward-Euler via Picard iteration. One CTA per batch
// element. Within a block of KBLK steps the state ys moves only O(K/sr),
// so: seed ys_est(t) = carry; sweep: d(t) = tanh([x_t, ys_est(t)]W1 + b1)W2/sr
// + b2/sr for ALL t in parallel; prefix-scan d -> refined ys_est; repeat
// NSWEEP times; advance carry; emit out[s] = exclusive state (== y_full[s]).
__global__ __launch_bounds__(512, 1)
void ode_picard_kernel(const float* __restrict__ x,
                       const float* __restrict__ W1,
                       const float* __restrict__ b1,
                       const float* __restrict__ b2,
                       const float* __restrict__ W2,
                       float* __restrict__ out,
                       int T) {
    extern __shared__ char smx[];
    ull*   w1dup  = (ull*)smx;             // [64][16] (w,w) pairs, state rows
    ull*   w2dup  = w1dup + 64 * 16;       // [64][16] (w,w) pairs, /sr
    ull*   w1xdup = w2dup + 64 * 16;       // [64] (w,w) W1 row 0
    ull*   b1dup  = w1xdup + 64;           // [64] (b,b)
    ull*   b2dup  = b1dup + 64;            // [16] (b2/sr, b2/sr)
    float* A      = (float*)(b2dup + 16);  // [16][KBLK] ys_est, dim-major
    float* WT     = A + 16 * KBLK;         // [16 warps][16] warp d-totals
    float* carry  = WT + 256;              // [16] block-start state

    const int b    = blockIdx.x;
    const int tid  = threadIdx.x;
    const int lane = tid & 31;
    const int wid  = tid >> 5;
    const float inv_sr = 1.0f / 44100.0f;
    const int nsteps = T - 1;

    // ---- prologue: duplicated-packed weights into smem ----
    if (tid < 64) {
        const int j = tid;
        w1xdup[j] = pk2(W1[j], W1[j]);
        b1dup[j]  = pk2(b1[j], b1[j]);
        for (int k = 0; k < 16; ++k) {
            const float w1v = W1[(k + 1) * 64 + j];
            w1dup[j * 16 + k] = pk2(w1v, w1v);
            const float w2v = W2[j * 16 + k] * inv_sr;
            w2dup[j * 16 + k] = pk2(w2v, w2v);
        }
    }
    if (tid < 16) {
        const float bv = b2[tid] * inv_sr;
        b2dup[tid] = pk2(bv, bv);
        carry[tid] = 0.0f;
    }
    __syncthreads();

    const int nblk = (nsteps + KBLK - 1) / KBLK;
    const int t1 = 2 * tid, t2 = 2 * tid + 1;   // this thread's local steps

    for (int blk = 0; blk < nblk; ++blk) {
        const int s1 = blk * KBLK + t1;
        const int s2 = s1 + 1;
        const bool v1 = s1 < nsteps, v2 = s2 < nsteps;
        const float x1 = v1 ? x[s1 * 32 + b] : 0.0f;
        const float x2 = v2 ? x[s2 * 32 + b] : 0.0f;
        const ull xpair = pk2(x1, x2);

        for (int sw = 0; sw < NSWEEP; ++sw) {
            __syncthreads();   // WT reuse + carry/A visibility

            // ---- ys estimate for my two timesteps ----
            ull ysp[16];
            if (sw == 0) {
#pragma unroll
                for (int k = 0; k < 16; ++k) {
                    const float c = carry[k];
                    ysp[k] = pk2(c, c);
                }
            } else {
#pragma unroll
                for (int k = 0; k < 16; ++k)
                    ysp[k] = pk2(A[k * KBLK + t1], A[k * KBLK + t2]);
            }

            // ---- d(t1), d(t2) packed: full 2-layer MLP over 64 hidden ----
            ull accd[16];
#pragma unroll
            for (int m = 0; m < 16; ++m) accd[m] = b2dup[m];
#pragma unroll 4
            for (int j = 0; j < 64; ++j) {
                ull ap = fma2(xpair, w1xdup[j], b1dup[j]);
#pragma unroll
                for (int k = 0; k < 16; ++k)
                    ap = fma2(ysp[k], w1dup[j * 16 + k], ap);
                float a1, a2;
                up2(ap, a1, a2);
                const ull hp = pk2(tanh_hw(a1), tanh_hw(a2));
#pragma unroll
                for (int m = 0; m < 16; ++m)
                    accd[m] = fma2(hp, w2dup[j * 16 + m], accd[m]);
            }

            // ---- unpack, zero invalid tail steps ----
            float d1[16], sig[16], inc[16];
#pragma unroll
            for (int m = 0; m < 16; ++m) {
                float dd1, dd2;
                up2(accd[m], dd1, dd2);
                if (!v1) dd1 = 0.0f;
                if (!v2) dd2 = 0.0f;
                d1[m]  = dd1;
                sig[m] = dd1 + dd2;
                inc[m] = sig[m];
            }

            // ---- warp inclusive scan of per-thread sums (16 dims) ----
#pragma unroll
            for (int off = 1; off < 32; off <<= 1) {
#pragma unroll
                for (int m = 0; m < 16; ++m) {
                    const float tv = __shfl_up_sync(FULL_MASK, inc[m], off);
                    if (lane >= off) inc[m] += tv;
                }
            }
            if (lane == 31) {
#pragma unroll
                for (int m = 0; m < 16; ++m) WT[wid * 16 + m] = inc[m];
            }
            __syncthreads();

            // ---- cross-warp offsets: lane m sums preceding warp totals ----
            float wofs = 0.0f;
            if (lane < 16) {
                wofs = carry[lane];
                for (int w = 0; w < wid; ++w) wofs += WT[w * 16 + lane];
            }

            // ---- exclusive states before my two steps ----
            float ys1[16], ys2[16];
#pragma unroll
            for (int m = 0; m < 16; ++m) {
                const float wo = __shfl_sync(FULL_MASK, wofs, m);
                ys1[m] = wo + (inc[m] - sig[m]);   // state before step s1
                ys2[m] = ys1[m] + d1[m];           // state before step s2
            }

            if (sw < NSWEEP - 1) {
#pragma unroll
                for (int m = 0; m < 16; ++m) {
                    A[m * KBLK + t1] = ys1[m];
                    A[m * KBLK + t2] = ys2[m];
                }
            } else {
                // final sweep: emit trajectory + advance carry
                if (v1) out[s1 * 32 + b] = ys1[0];
                if (v2) out[s2 * 32 + b] = ys2[0];
                if (wid == 15 && lane < 16)
                    carry[lane] = wofs + WT[15 * 16 + lane];
            }
        }
    }

    __syncthreads();
    if (tid == 0) out[nsteps * 32 + b] = carry[0];  // y_full[T-1]
}

extern "C" void kernel_launch(void* const* d_in, const int* in_sizes, int n_in,
                              void* d_out, int out_size) {
    const float* x  = (const float*)d_in[0];
    const float* W1 = (const float*)d_in[1];
    const float* b1 = (const float*)d_in[2];
    const float* W2 = (const float*)d_in[3];
    const float* b2 = (const float*)d_in[4];
    float* out = (float*)d_out;

    const int T = in_sizes[0] / 32;   // x is (T, B=32, F=1)

    const size_t smem_bytes =
        (64 * 16 + 64 * 16 + 64 + 64 + 16) * sizeof(ull) +   // packed weights
        (16 * KBLK + 256 + 16) * sizeof(float) + 256;        // A + WT + carry
    cudaFuncSetAttribute(ode_picard_kernel,
                         cudaFuncAttributeMaxDynamicSharedMemorySize,
                         (int)smem_bytes);
    ode_picard_kernel<<<32, 512, smem_bytes>>>(x, W1, b1, b2, W2, out, T);
}

// round 12
// speedup vs baseline: 8.5156x; 2.9379x over previous
#include <cuda_runtime.h>
#include <cstdint>
#include <math.h>

#define FULL_MASK 0xffffffffu
typedef unsigned long long ull;

// ---- f32x2 packed-math helpers ----
__device__ __forceinline__ ull pk2(float lo, float hi) {
    ull r; asm("mov.b64 %0,{%1,%2};" : "=l"(r) : "f"(lo), "f"(hi)); return r;
}
__device__ __forceinline__ void up2(ull v, float& lo, float& hi) {
    asm("mov.b64 {%0,%1},%2;" : "=f"(lo), "=f"(hi) : "l"(v));
}
__device__ __forceinline__ ull fma2(ull a, ull b, ull c) {
    ull d; asm("fma.rn.f32x2 %0,%1,%2,%3;" : "=l"(d) : "l"(a), "l"(b), "l"(c)); return d;
}
__device__ __forceinline__ float tanh_hw(float x) {
    float y; asm("tanh.approx.f32 %0, %1;" : "=f"(y) : "f"(x)); return y;
}
__device__ __forceinline__ uint32_t smem_u32(const void* p) {
    uint32_t a;
    asm("{ .reg .u64 t; cvta.to.shared.u64 t, %1; cvt.u32.u64 %0, t; }"
        : "=r"(a) : "l"(p));
    return a;
}
// read a float from the same smem offset in cluster CTA `rank`
__device__ __forceinline__ float ld_cluster_f32(uint32_t my_addr, uint32_t rank) {
    uint32_t ra; float v;
    asm volatile("mapa.shared::cluster.u32 %0, %1, %2;" : "=r"(ra) : "r"(my_addr), "r"(rank));
    asm volatile("ld.shared::cluster.f32 %0, [%1];" : "=f"(v) : "r"(ra));
    return v;
}
#define CLUSTER_SYNC() do { \
    asm volatile("barrier.cluster.arrive.aligned;" ::: "memory"); \
    asm volatile("barrier.cluster.wait.aligned;"   ::: "memory"); } while (0)

#define KCTA   1024     // timesteps per CTA (2 per thread, 512 threads)
#define CSZ    4        // CTAs per cluster (one cluster per batch element)
#define KSUPER (KCTA * CSZ)
#define NSWEEP 4        // Picard sweeps per superblock (lambda*K ~ 0.03)

// Parallel-in-time forward-Euler via Picard iteration, cluster edition.
// One 4-CTA cluster per batch element; each superblock of KSUPER=4096 steps
// is swept in parallel by the 4 ranks (KCTA steps each). The prefix scan is
// closed across ranks by exchanging 16-dim block totals through DSMEM.
// Carry across superblocks is replicated per-rank (identical arithmetic).
__global__ __launch_bounds__(512, 1) __cluster_dims__(CSZ, 1, 1)
void ode_picard_kernel(const float* __restrict__ x,
                       const float* __restrict__ W1,
                       const float* __restrict__ b1,
                       const float* __restrict__ b2,
                       const float* __restrict__ W2,
                       float* __restrict__ out,
                       int T) {
    extern __shared__ char smx[];
    ull*   w1dup  = (ull*)smx;             // [64][16] (w,w) pairs, state rows
    ull*   w2dup  = w1dup + 64 * 16;       // [64][16] (w,w) pairs, /sr
    ull*   w1xdup = w2dup + 64 * 16;       // [64] (w,w) W1 row 0
    ull*   b1dup  = w1xdup + 64;           // [64] (b,b)
    ull*   b2dup  = b1dup + 64;            // [16] (b2/sr, b2/sr)
    float* A      = (float*)(b2dup + 16);  // [16][KCTA] ys_est, dim-major
    float* WT     = A + 16 * KCTA;         // [16 warps][16] warp d-totals
    float* carry  = WT + 256;              // [16] superblock-start state (replica)
    float* rtot   = carry + 16;            // [16] this rank's d total (DSMEM-read)
    float* rbase  = rtot + 16;             // [16] carry + totals of lower ranks
    float* cnew   = rbase + 16;            // [16] next carry

    const int b    = blockIdx.x / CSZ;     // batch element (clusters contiguous)
    uint32_t rank;
    asm("mov.u32 %0, %%cluster_ctarank;" : "=r"(rank));
    const int tid  = threadIdx.x;
    const int lane = tid & 31;
    const int wid  = tid >> 5;
    const float inv_sr = 1.0f / 44100.0f;
    const int nsteps = T - 1;

    // ---- prologue: duplicated-packed weights into smem ----
    if (tid < 64) {
        const int j = tid;
        w1xdup[j] = pk2(W1[j], W1[j]);
        b1dup[j]  = pk2(b1[j], b1[j]);
        for (int k = 0; k < 16; ++k) {
            const float w1v = W1[(k + 1) * 64 + j];
            w1dup[j * 16 + k] = pk2(w1v, w1v);
            const float w2v = W2[j * 16 + k] * inv_sr;
            w2dup[j * 16 + k] = pk2(w2v, w2v);
        }
    }
    if (tid < 16) carry[tid] = 0.0f;
    __syncthreads();

    const uint32_t rtot_addr = smem_u32(rtot + (tid & 15));
    const int nsuper = (nsteps + KSUPER - 1) / KSUPER;
    const int t1 = 2 * tid, t2 = 2 * tid + 1;   // local steps within my KCTA

    for (int blk = 0; blk < nsuper; ++blk) {
        const int s1 = blk * KSUPER + (int)rank * KCTA + t1;
        const int s2 = s1 + 1;
        const bool v1 = s1 < nsteps, v2 = s2 < nsteps;
        const float x1 = v1 ? x[s1 * 32 + b] : 0.0f;
        const float x2 = v2 ? x[s2 * 32 + b] : 0.0f;
        const ull xpair = pk2(x1, x2);

        for (int sw = 0; sw < NSWEEP; ++sw) {
            __syncthreads();   // A/carry/WT visibility across sweeps

            // ---- ys estimate for my two timesteps ----
            ull ysp[16];
            if (sw == 0) {
#pragma unroll
                for (int k = 0; k < 16; ++k) {
                    const float c = carry[k];
                    ysp[k] = pk2(c, c);
                }
            } else {
#pragma unroll
                for (int k = 0; k < 16; ++k)
                    ysp[k] = pk2(A[k * KCTA + t1], A[k * KCTA + t2]);
            }

            // ---- d(t1), d(t2) packed: full 2-layer MLP over 64 hidden ----
            ull accd[16];
#pragma unroll
            for (int m = 0; m < 16; ++m) accd[m] = b2dup[m];
#pragma unroll 4
            for (int j = 0; j < 64; ++j) {
                ull ap = fma2(xpair, w1xdup[j], b1dup[j]);
#pragma unroll
                for (int k = 0; k < 16; ++k)
                    ap = fma2(ysp[k], w1dup[j * 16 + k], ap);
                float a1, a2;
                up2(ap, a1, a2);
                const ull hp = pk2(tanh_hw(a1), tanh_hw(a2));
#pragma unroll
                for (int m = 0; m < 16; ++m)
                    accd[m] = fma2(hp, w2dup[j * 16 + m], accd[m]);
            }

            // ---- unpack, zero invalid tail steps ----
            float d1[16], sig[16], inc[16];
#pragma unroll
            for (int m = 0; m < 16; ++m) {
                float dd1, dd2;
                up2(accd[m], dd1, dd2);
                if (!v1) dd1 = 0.0f;
                if (!v2) dd2 = 0.0f;
                d1[m]  = dd1;
                sig[m] = dd1 + dd2;
                inc[m] = sig[m];
            }

            // ---- warp inclusive scan of per-thread sums (16 dims) ----
#pragma unroll
            for (int off = 1; off < 32; off <<= 1) {
#pragma unroll
                for (int m = 0; m < 16; ++m) {
                    const float tv = __shfl_up_sync(FULL_MASK, inc[m], off);
                    if (lane >= off) inc[m] += tv;
                }
            }
            if (lane == 31) {
#pragma unroll
                for (int m = 0; m < 16; ++m) WT[wid * 16 + m] = inc[m];
            }
            __syncthreads();

            // ---- this rank's block total -> rtot (published for peers) ----
            if (tid < 16) {
                float s = 0.0f;
                for (int w = 0; w < 16; ++w) s += WT[w * 16 + tid];
                rtot[tid] = s;
            }
            CLUSTER_SYNC();   // rtot valid in every rank's smem

            // ---- cross-rank offsets + next carry (identical in all ranks) ----
            if (tid < 16) {
                float base = carry[tid];
                float all  = 0.0f;
                for (int r = 0; r < CSZ; ++r) {
                    const float v = ld_cluster_f32(rtot_addr, (uint32_t)r);
                    all += v;
                    if (r < (int)rank) base += v;
                }
                rbase[tid] = base;
                cnew[tid]  = carry[tid] + all;
            }
            CLUSTER_SYNC();   // rbase/cnew visible; peers done reading rtot

            // ---- cross-warp offsets within my CTA ----
            float wofs = 0.0f;
            if (lane < 16) {
                wofs = rbase[lane];
                for (int w = 0; w < wid; ++w) wofs += WT[w * 16 + lane];
            }

            // ---- exclusive states before my two steps ----
            float ys1[16], ys2[16];
#pragma unroll
            for (int m = 0; m < 16; ++m) {
                const float wo = __shfl_sync(FULL_MASK, wofs, m);
                ys1[m] = wo + (inc[m] - sig[m]);   // state before step s1
                ys2[m] = ys1[m] + d1[m];           // state before step s2
            }

            if (sw < NSWEEP - 1) {
#pragma unroll
                for (int m = 0; m < 16; ++m) {
                    A[m * KCTA + t1] = ys1[m];
                    A[m * KCTA + t2] = ys2[m];
                }
            } else {
                // final sweep: emit trajectory + advance carry replica
                if (v1) out[s1 * 32 + b] = ys1[0];
                if (v2) out[s2 * 32 + b] = ys2[0];
                if (tid < 16) carry[tid] = cnew[tid];
            }
        }
    }

    __syncthreads();
    if (rank == 0 && tid == 0) out[nsteps * 32 + b] = carry[0];  // y_full[T-1]
}

extern "C" void kernel_launch(void* const* d_in, const int* in_sizes, int n_in,
                              void* d_out, int out_size) {
    const float* x  = (const float*)d_in[0];
    const float* W1 = (const float*)d_in[1];
    const float* b1 = (const float*)d_in[2];
    const float* W2 = (const float*)d_in[3];
    const float* b2 = (const float*)d_in[4];
    float* out = (float*)d_out;

    const int T = in_sizes[0] / 32;   // x is (T, B=32, F=1)

    const size_t smem_bytes =
        (64 * 16 + 64 * 16 + 64 + 64 + 16) * sizeof(ull) +       // packed weights
        (16 * KCTA + 256 + 16 * 4) * sizeof(float) + 256;        // A + WT + vecs
    cudaFuncSetAttribute(ode_picard_kernel,
                         cudaFuncAttributeMaxDynamicSharedMemorySize,
                         (int)smem_bytes);
    ode_picard_kernel<<<32 * CSZ, 512, smem_bytes>>>(x, W1, b1, b2, W2, out, T);
}

// round 13
// speedup vs baseline: 11.1364x; 1.3078x over previous
#include <cuda_runtime.h>
#include <cstdint>
#include <math.h>

#define FULL_MASK 0xffffffffu
typedef unsigned long long ull;

// ---- f32x2 packed-math helpers ----
__device__ __forceinline__ ull pk2(float lo, float hi) {
    ull r; asm("mov.b64 %0,{%1,%2};" : "=l"(r) : "f"(lo), "f"(hi)); return r;
}
__device__ __forceinline__ void up2(ull v, float& lo, float& hi) {
    asm("mov.b64 {%0,%1},%2;" : "=f"(lo), "=f"(hi) : "l"(v));
}
__device__ __forceinline__ ull fma2(ull a, ull b, ull c) {
    ull d; asm("fma.rn.f32x2 %0,%1,%2,%3;" : "=l"(d) : "l"(a), "l"(b), "l"(c)); return d;
}
__device__ __forceinline__ float tanh_hw(float x) {
    float y; asm("tanh.approx.f32 %0, %1;" : "=f"(y) : "f"(x)); return y;
}
__device__ __forceinline__ uint32_t smem_u32(const void* p) {
    uint32_t a;
    asm("{ .reg .u64 t; cvta.to.shared.u64 t, %1; cvt.u32.u64 %0, t; }"
        : "=r"(a) : "l"(p));
    return a;
}
// read a float from the same smem offset in cluster CTA `rank`
__device__ __forceinline__ float ld_cluster_f32(uint32_t my_addr, uint32_t rank) {
    uint32_t ra; float v;
    asm volatile("mapa.shared::cluster.u32 %0, %1, %2;" : "=r"(ra) : "r"(my_addr), "r"(rank));
    asm volatile("ld.shared::cluster.f32 %0, [%1];" : "=f"(v) : "r"(ra));
    return v;
}
#define CLUSTER_SYNC() do { \
    asm volatile("barrier.cluster.arrive.aligned;" ::: "memory"); \
    asm volatile("barrier.cluster.wait.aligned;"   ::: "memory"); } while (0)

#define KCTA   1024     // timesteps per CTA (2 per thread, 512 threads)
#define CSZ    4        // CTAs per cluster (one cluster per batch element)
#define KSUPER (KCTA * CSZ)
#define NSWEEP 3        // Picard sweeps; residual ~ e0*(lambda*K)^3, bounded << 1e-3

// Parallel-in-time forward-Euler via Picard iteration, cluster edition.
// One 4-CTA cluster per batch element; superblocks of KSUPER=4096 steps are
// swept in parallel by the 4 ranks; prefix scan closed across ranks via
// DSMEM. Weight streams are 16-byte vectorized (LDS.128): per hidden unit
// the loop issues 17 vector loads instead of 34 scalar ones.
__global__ __launch_bounds__(512, 1) __cluster_dims__(CSZ, 1, 1)
void ode_picard_kernel(const float* __restrict__ x,
                       const float* __restrict__ W1,
                       const float* __restrict__ b1,
                       const float* __restrict__ b2,
                       const float* __restrict__ W2,
                       float* __restrict__ out,
                       int T) {
    extern __shared__ char smx[];
    ull*        w1dup = (ull*)smx;              // [64][16] (w,w) pairs, state rows
    ull*        w2dup = w1dup + 64 * 16;        // [64][16] (w,w) pairs, /sr
    ulonglong2* xbv   = (ulonglong2*)(w2dup + 64 * 16); // [64] {(w1x,w1x),(b1,b1)}
    ull*        b2dup = (ull*)(xbv + 64);       // [16] (b2/sr, b2/sr)
    float*      A     = (float*)(b2dup + 16);   // [16][KCTA] ys_est, dim-major
    float*      WT    = A + 16 * KCTA;          // [16 warps][16] warp d-totals
    float*      carry = WT + 256;               // [16] superblock-start state
    float*      rtot  = carry + 16;             // [16] this rank's d total
    float*      rbase = rtot + 16;              // [16] carry + lower-rank totals
    float*      cnew  = rbase + 16;             // [16] next carry

    const int b = blockIdx.x / CSZ;             // batch element
    uint32_t rank;
    asm("mov.u32 %0, %%cluster_ctarank;" : "=r"(rank));
    const int tid  = threadIdx.x;
    const int lane = tid & 31;
    const int wid  = tid >> 5;
    const float inv_sr = 1.0f / 44100.0f;
    const int nsteps = T - 1;

    // ---- prologue: duplicated-packed weights into smem ----
    if (tid < 64) {
        const int j = tid;
        ulonglong2 xb;
        xb.x = pk2(W1[j], W1[j]);
        xb.y = pk2(b1[j], b1[j]);
        xbv[j] = xb;
        for (int k = 0; k < 16; ++k) {
            const float w1v = W1[(k + 1) * 64 + j];
            w1dup[j * 16 + k] = pk2(w1v, w1v);
            const float w2v = W2[j * 16 + k] * inv_sr;
            w2dup[j * 16 + k] = pk2(w2v, w2v);
        }
    }
    if (tid < 16) {
        const float bv = b2[tid] * inv_sr;
        b2dup[tid] = pk2(bv, bv);
        carry[tid] = 0.0f;
    }
    __syncthreads();

    const uint32_t rtot_addr = smem_u32(rtot + (tid & 15));
    const int nsuper = (nsteps + KSUPER - 1) / KSUPER;
    const int t1 = 2 * tid, t2 = 2 * tid + 1;   // local steps within my KCTA

    for (int blk = 0; blk < nsuper; ++blk) {
        const int s1 = blk * KSUPER + (int)rank * KCTA + t1;
        const int s2 = s1 + 1;
        const bool v1 = s1 < nsteps, v2 = s2 < nsteps;
        const float x1 = v1 ? x[s1 * 32 + b] : 0.0f;
        const float x2 = v2 ? x[s2 * 32 + b] : 0.0f;
        const ull xpair = pk2(x1, x2);

        for (int sw = 0; sw < NSWEEP; ++sw) {
            __syncthreads();   // A/carry/WT visibility across sweeps

            // ---- ys estimate for my two timesteps ----
            ull ysp[16];
            if (sw == 0) {
#pragma unroll
                for (int k = 0; k < 16; ++k) {
                    const float c = carry[k];
                    ysp[k] = pk2(c, c);
                }
            } else {
#pragma unroll
                for (int k = 0; k < 16; ++k)
                    ysp[k] = pk2(A[k * KCTA + t1], A[k * KCTA + t2]);
            }

            // ---- d(t1), d(t2) packed: 2-layer MLP, vectorized weights ----
            ull accd[16];
#pragma unroll
            for (int m = 0; m < 16; ++m) accd[m] = b2dup[m];
#pragma unroll 4
            for (int j = 0; j < 64; ++j) {
                const ulonglong2 xb = xbv[j];
                ull ap = fma2(xpair, xb.x, xb.y);
                const ulonglong2* w1r =
                    reinterpret_cast<const ulonglong2*>(w1dup + j * 16);
#pragma unroll
                for (int kk = 0; kk < 8; ++kk) {
                    const ulonglong2 w = w1r[kk];          // LDS.128
                    ap = fma2(ysp[2 * kk],     w.x, ap);
                    ap = fma2(ysp[2 * kk + 1], w.y, ap);
                }
                float a1, a2;
                up2(ap, a1, a2);
                const ull hp = pk2(tanh_hw(a1), tanh_hw(a2));
                const ulonglong2* w2r =
                    reinterpret_cast<const ulonglong2*>(w2dup + j * 16);
#pragma unroll
                for (int kk = 0; kk < 8; ++kk) {
                    const ulonglong2 w = w2r[kk];          // LDS.128
                    accd[2 * kk]     = fma2(hp, w.x, accd[2 * kk]);
                    accd[2 * kk + 1] = fma2(hp, w.y, accd[2 * kk + 1]);
                }
            }

            // ---- unpack, zero invalid tail steps ----
            float d1[16], sig[16], inc[16];
#pragma unroll
            for (int m = 0; m < 16; ++m) {
                float dd1, dd2;
                up2(accd[m], dd1, dd2);
                if (!v1) dd1 = 0.0f;
                if (!v2) dd2 = 0.0f;
                d1[m]  = dd1;
                sig[m] = dd1 + dd2;
                inc[m] = sig[m];
            }

            // ---- warp inclusive scan of per-thread sums (16 dims) ----
#pragma unroll
            for (int off = 1; off < 32; off <<= 1) {
#pragma unroll
                for (int m = 0; m < 16; ++m) {
                    const float tv = __shfl_up_sync(FULL_MASK, inc[m], off);
                    if (lane >= off) inc[m] += tv;
                }
            }
            if (lane == 31) {
#pragma unroll
                for (int m = 0; m < 16; ++m) WT[wid * 16 + m] = inc[m];
            }
            __syncthreads();

            // ---- this rank's block total -> rtot (published for peers) ----
            if (tid < 16) {
                float s = 0.0f;
                for (int w = 0; w < 16; ++w) s += WT[w * 16 + tid];
                rtot[tid] = s;
            }
            CLUSTER_SYNC();   // rtot valid in every rank's smem

            // ---- cross-rank offsets + next carry (identical in all ranks) ----
            if (tid < 16) {
                float base = carry[tid];
                float all  = 0.0f;
                for (int r = 0; r < CSZ; ++r) {
                    const float v = ld_cluster_f32(rtot_addr, (uint32_t)r);
                    all += v;
                    if (r < (int)rank) base += v;
                }
                rbase[tid] = base;
                cnew[tid]  = carry[tid] + all;
            }
            CLUSTER_SYNC();   // rbase/cnew visible; peers done reading rtot

            // ---- cross-warp offsets within my CTA ----
            float wofs = 0.0f;
            if (lane < 16) {
                wofs = rbase[lane];
                for (int w = 0; w < wid; ++w) wofs += WT[w * 16 + lane];
            }

            // ---- exclusive states before my two steps ----
            float ys1[16], ys2[16];
#pragma unroll
            for (int m = 0; m < 16; ++m) {
                const float wo = __shfl_sync(FULL_MASK, wofs, m);
                ys1[m] = wo + (inc[m] - sig[m]);   // state before step s1
                ys2[m] = ys1[m] + d1[m];           // state before step s2
            }

            if (sw < NSWEEP - 1) {
#pragma unroll
                for (int m = 0; m < 16; ++m) {
                    A[m * KCTA + t1] = ys1[m];
                    A[m * KCTA + t2] = ys2[m];
                }
            } else {
                // final sweep: emit trajectory + advance carry replica
                if (v1) out[s1 * 32 + b] = ys1[0];
                if (v2) out[s2 * 32 + b] = ys2[0];
                if (tid < 16) carry[tid] = cnew[tid];
            }
        }
    }

    __syncthreads();
    if (rank == 0 && tid == 0) out[nsteps * 32 + b] = carry[0];  // y_full[T-1]
}

extern "C" void kernel_launch(void* const* d_in, const int* in_sizes, int n_in,
                              void* d_out, int out_size) {
    const float* x  = (const float*)d_in[0];
    const float* W1 = (const float*)d_in[1];
    const float* b1 = (const float*)d_in[2];
    const float* W2 = (const float*)d_in[3];
    const float* b2 = (const float*)d_in[4];
    float* out = (float*)d_out;

    const int T = in_sizes[0] / 32;   // x is (T, B=32, F=1)

    const size_t smem_bytes =
        (64 * 16 + 64 * 16 + 16) * sizeof(ull) +           // w1dup, w2dup, b2dup
        64 * sizeof(ulonglong2) +                          // xbv
        (16 * KCTA + 256 + 16 * 4) * sizeof(float) + 256;  // A + WT + vecs
    cudaFuncSetAttribute(ode_picard_kernel,
                         cudaFuncAttributeMaxDynamicSharedMemorySize,
                         (int)smem_bytes);
    ode_picard_kernel<<<32 * CSZ, 512, smem_bytes>>>(x, W1, b1, b2, W2, out, T);
}

// round 14
// speedup vs baseline: 14.4592x; 1.2984x over previous
#include <cuda_runtime.h>
#include <cstdint>
#include <math.h>

#define FULL_MASK 0xffffffffu
typedef unsigned long long ull;

// ---- f32x2 packed-math helpers ----
__device__ __forceinline__ ull pk2(float lo, float hi) {
    ull r; asm("mov.b64 %0,{%1,%2};" : "=l"(r) : "f"(lo), "f"(hi)); return r;
}
__device__ __forceinline__ void up2(ull v, float& lo, float& hi) {
    asm("mov.b64 {%0,%1},%2;" : "=f"(lo), "=f"(hi) : "l"(v));
}
__device__ __forceinline__ ull fma2(ull a, ull b, ull c) {
    ull d; asm("fma.rn.f32x2 %0,%1,%2,%3;" : "=l"(d) : "l"(a), "l"(b), "l"(c)); return d;
}
__device__ __forceinline__ float tanh_hw(float x) {
    float y; asm("tanh.approx.f32 %0, %1;" : "=f"(y) : "f"(x)); return y;
}
__device__ __forceinline__ uint32_t smem_u32(const void* p) {
    uint32_t a;
    asm("{ .reg .u64 t; cvta.to.shared.u64 t, %1; cvt.u32.u64 %0, t; }"
        : "=r"(a) : "l"(p));
    return a;
}
__device__ __forceinline__ float ld_cluster_f32(uint32_t my_addr, uint32_t rank) {
    uint32_t ra; float v;
    asm volatile("mapa.shared::cluster.u32 %0, %1, %2;" : "=r"(ra) : "r"(my_addr), "r"(rank));
    asm volatile("ld.shared::cluster.f32 %0, [%1];" : "=f"(v) : "r"(ra));
    return v;
}
#define CLUSTER_SYNC() do { \
    asm volatile("barrier.cluster.arrive.aligned;" ::: "memory"); \
    asm volatile("barrier.cluster.wait.aligned;"   ::: "memory"); } while (0)

#define THREADS 256
#define TPT     4          // timesteps per thread (two packed pair-streams)
#define KCTA    (THREADS * TPT)   // 1024
#define CSZ     4
#define KSUPER  (KCTA * CSZ)
#define NSWEEP  3
#define NWARP   (THREADS / 32)    // 8

// Parallel-in-time Picard, cluster edition, 4 timesteps per thread.
// Every duplicated (w,w) weight load now feeds 4 fma2 (two t-pair streams),
// halving LDS pressure per unit work; ys_est I/O is float4 per dim.
__global__ __launch_bounds__(THREADS, 1) __cluster_dims__(CSZ, 1, 1)
void ode_picard_kernel(const float* __restrict__ x,
                       const float* __restrict__ W1,
                       const float* __restrict__ b1,
                       const float* __restrict__ b2,
                       const float* __restrict__ W2,
                       float* __restrict__ out,
                       int T) {
    extern __shared__ char smx[];
    ull*        w1dup = (ull*)smx;                       // [64][16] (w,w)
    ull*        w2dup = w1dup + 64 * 16;                 // [64][16] (w,w)/sr
    ulonglong2* xbv   = (ulonglong2*)(w2dup + 64 * 16);  // [64] {(w1x,w1x),(b1,b1)}
    ull*        b2dup = (ull*)(xbv + 64);                // [16] (b2/sr, b2/sr)
    float*      A     = (float*)(b2dup + 16);            // [16][KCTA] ys_est
    float*      WT    = A + 16 * KCTA;                   // [8 warps][16]
    float*      carry = WT + NWARP * 16;                 // [16]
    float*      rtot  = carry + 16;                      // [16]
    float*      rbase = rtot + 16;                       // [16]
    float*      cnew  = rbase + 16;                      // [16]

    const int b = blockIdx.x / CSZ;
    uint32_t rank;
    asm("mov.u32 %0, %%cluster_ctarank;" : "=r"(rank));
    const int tid  = threadIdx.x;
    const int lane = tid & 31;
    const int wid  = tid >> 5;
    const float inv_sr = 1.0f / 44100.0f;
    const int nsteps = T - 1;

    // ---- prologue: duplicated-packed weights into smem ----
    if (tid < 64) {
        const int j = tid;
        ulonglong2 xb;
        xb.x = pk2(W1[j], W1[j]);
        xb.y = pk2(b1[j], b1[j]);
        xbv[j] = xb;
        for (int k = 0; k < 16; ++k) {
            const float w1v = W1[(k + 1) * 64 + j];
            w1dup[j * 16 + k] = pk2(w1v, w1v);
            const float w2v = W2[j * 16 + k] * inv_sr;
            w2dup[j * 16 + k] = pk2(w2v, w2v);
        }
    }
    if (tid < 16) {
        const float bv = b2[tid] * inv_sr;
        b2dup[tid] = pk2(bv, bv);
        carry[tid] = 0.0f;
    }
    __syncthreads();

    const uint32_t rtot_addr = smem_u32(rtot + (tid & 15));
    const int nsuper = (nsteps + KSUPER - 1) / KSUPER;
    const int tl = TPT * tid;                // first local step of this thread

    for (int blk = 0; blk < nsuper; ++blk) {
        const int s0 = blk * KSUPER + (int)rank * KCTA + tl;
        const bool v1 = s0 < nsteps,     v2 = s0 + 1 < nsteps;
        const bool v3 = s0 + 2 < nsteps, v4 = s0 + 3 < nsteps;
        const float x1 = v1 ? x[(s0)     * 32 + b] : 0.0f;
        const float x2 = v2 ? x[(s0 + 1) * 32 + b] : 0.0f;
        const float x3 = v3 ? x[(s0 + 2) * 32 + b] : 0.0f;
        const float x4 = v4 ? x[(s0 + 3) * 32 + b] : 0.0f;
        const ull xpA = pk2(x1, x2);
        const ull xpB = pk2(x3, x4);

        for (int sw = 0; sw < NSWEEP; ++sw) {
            __syncthreads();

            // ---- ys estimates for my four timesteps ----
            ull yspA[16], yspB[16];
            if (sw == 0) {
#pragma unroll
                for (int k = 0; k < 16; ++k) {
                    const float c = carry[k];
                    yspA[k] = pk2(c, c);
                    yspB[k] = yspA[k];
                }
            } else {
#pragma unroll
                for (int k = 0; k < 16; ++k) {
                    const float4 f = *reinterpret_cast<const float4*>(A + k * KCTA + tl);
                    yspA[k] = pk2(f.x, f.y);
                    yspB[k] = pk2(f.z, f.w);
                }
            }

            // ---- d for 4 timesteps: 2-layer MLP, shared weight loads ----
            ull accA[16], accB[16];
#pragma unroll
            for (int m = 0; m < 16; ++m) { accA[m] = b2dup[m]; accB[m] = b2dup[m]; }
#pragma unroll 2
            for (int j = 0; j < 64; ++j) {
                const ulonglong2 xb = xbv[j];
                ull apA = fma2(xpA, xb.x, xb.y);
                ull apB = fma2(xpB, xb.x, xb.y);
                const ulonglong2* w1r =
                    reinterpret_cast<const ulonglong2*>(w1dup + j * 16);
#pragma unroll
                for (int kk = 0; kk < 8; ++kk) {
                    const ulonglong2 w = w1r[kk];          // one LDS.128, 4 fma2
                    apA = fma2(yspA[2 * kk],     w.x, apA);
                    apB = fma2(yspB[2 * kk],     w.x, apB);
                    apA = fma2(yspA[2 * kk + 1], w.y, apA);
                    apB = fma2(yspB[2 * kk + 1], w.y, apB);
                }
                float a1, a2, a3, a4;
                up2(apA, a1, a2);
                up2(apB, a3, a4);
                const ull hpA = pk2(tanh_hw(a1), tanh_hw(a2));
                const ull hpB = pk2(tanh_hw(a3), tanh_hw(a4));
                const ulonglong2* w2r =
                    reinterpret_cast<const ulonglong2*>(w2dup + j * 16);
#pragma unroll
                for (int kk = 0; kk < 8; ++kk) {
                    const ulonglong2 w = w2r[kk];          // one LDS.128, 4 fma2
                    accA[2 * kk]     = fma2(hpA, w.x, accA[2 * kk]);
                    accB[2 * kk]     = fma2(hpB, w.x, accB[2 * kk]);
                    accA[2 * kk + 1] = fma2(hpA, w.y, accA[2 * kk + 1]);
                    accB[2 * kk + 1] = fma2(hpB, w.y, accB[2 * kk + 1]);
                }
            }

            // ---- unpack, mask tail, build per-thread cumulative sums ----
            float c1[16], c2[16], c3[16], inc[16], sig[16];
#pragma unroll
            for (int m = 0; m < 16; ++m) {
                float d1, d2, d3, d4;
                up2(accA[m], d1, d2);
                up2(accB[m], d3, d4);
                if (!v1) d1 = 0.0f;
                if (!v2) d2 = 0.0f;
                if (!v3) d3 = 0.0f;
                if (!v4) d4 = 0.0f;
                c1[m]  = d1;
                c2[m]  = d1 + d2;
                c3[m]  = c2[m] + d3;
                sig[m] = c3[m] + d4;
                inc[m] = sig[m];
            }

            // ---- warp inclusive scan of per-thread sums (16 dims) ----
#pragma unroll
            for (int off = 1; off < 32; off <<= 1) {
#pragma unroll
                for (int m = 0; m < 16; ++m) {
                    const float tv = __shfl_up_sync(FULL_MASK, inc[m], off);
                    if (lane >= off) inc[m] += tv;
                }
            }
            if (lane == 31) {
#pragma unroll
                for (int m = 0; m < 16; ++m) WT[wid * 16 + m] = inc[m];
            }
            __syncthreads();

            // ---- this rank's block total -> rtot ----
            if (tid < 16) {
                float s = 0.0f;
                for (int w = 0; w < NWARP; ++w) s += WT[w * 16 + tid];
                rtot[tid] = s;
            }
            CLUSTER_SYNC();

            // ---- cross-rank offsets + next carry ----
            if (tid < 16) {
                float base = carry[tid];
                float all  = 0.0f;
                for (int r = 0; r < CSZ; ++r) {
                    const float v = ld_cluster_f32(rtot_addr, (uint32_t)r);
                    all += v;
                    if (r < (int)rank) base += v;
                }
                rbase[tid] = base;
                cnew[tid]  = carry[tid] + all;
            }
            CLUSTER_SYNC();

            // ---- cross-warp offsets within my CTA ----
            float wofs = 0.0f;
            if (lane < 16) {
                wofs = rbase[lane];
                for (int w = 0; w < wid; ++w) wofs += WT[w * 16 + lane];
            }

            // ---- exclusive states before my four steps ----
            if (sw < NSWEEP - 1) {
#pragma unroll
                for (int m = 0; m < 16; ++m) {
                    const float wo = __shfl_sync(FULL_MASK, wofs, m);
                    const float ex = wo + (inc[m] - sig[m]);
                    float4 f;
                    f.x = ex;
                    f.y = ex + c1[m];
                    f.z = ex + c2[m];
                    f.w = ex + c3[m];
                    *reinterpret_cast<float4*>(A + m * KCTA + tl) = f;
                }
            } else {
                // final sweep: emit trajectory + advance carry replica
                {
                    const float wo = __shfl_sync(FULL_MASK, wofs, 0);
                    const float ex = wo + (inc[0] - sig[0]);
                    if (v1) out[(s0)     * 32 + b] = ex;
                    if (v2) out[(s0 + 1) * 32 + b] = ex + c1[0];
                    if (v3) out[(s0 + 2) * 32 + b] = ex + c2[0];
                    if (v4) out[(s0 + 3) * 32 + b] = ex + c3[0];
                }
                if (tid < 16) carry[tid] = cnew[tid];
            }
        }
    }

    __syncthreads();
    if (rank == 0 && tid == 0) out[nsteps * 32 + b] = carry[0];  // y_full[T-1]
}

extern "C" void kernel_launch(void* const* d_in, const int* in_sizes, int n_in,
                              void* d_out, int out_size) {
    const float* x  = (const float*)d_in[0];
    const float* W1 = (const float*)d_in[1];
    const float* b1 = (const float*)d_in[2];
    const float* W2 = (const float*)d_in[3];
    const float* b2 = (const float*)d_in[4];
    float* out = (float*)d_out;

    const int T = in_sizes[0] / 32;   // x is (T, B=32, F=1)

    const size_t smem_bytes =
        (64 * 16 + 64 * 16 + 16) * sizeof(ull) +
        64 * sizeof(ulonglong2) +
        (16 * KCTA + NWARP * 16 + 16 * 4) * sizeof(float) + 256;
    cudaFuncSetAttribute(ode_picard_kernel,
                         cudaFuncAttributeMaxDynamicSharedMemorySize,
                         (int)smem_bytes);
    ode_picard_kernel<<<32 * CSZ, THREADS, smem_bytes>>>(x, W1, b1, b2, W2, out, T);
}

// round 15
// speedup vs baseline: 16.5871x; 1.1472x over previous
#include <cuda_runtime.h>
#include <cstdint>
#include <math.h>

#define FULL_MASK 0xffffffffu
typedef unsigned long long ull;

// ---- f32x2 packed-math helpers ----
__device__ __forceinline__ ull pk2(float lo, float hi) {
    ull r; asm("mov.b64 %0,{%1,%2};" : "=l"(r) : "f"(lo), "f"(hi)); return r;
}
__device__ __forceinline__ void up2(ull v, float& lo, float& hi) {
    asm("mov.b64 {%0,%1},%2;" : "=f"(lo), "=f"(hi) : "l"(v));
}
__device__ __forceinline__ ull fma2(ull a, ull b, ull c) {
    ull d; asm("fma.rn.f32x2 %0,%1,%2,%3;" : "=l"(d) : "l"(a), "l"(b), "l"(c)); return d;
}
__device__ __forceinline__ float tanh_hw(float x) {
    float y; asm("tanh.approx.f32 %0, %1;" : "=f"(y) : "f"(x)); return y;
}
__device__ __forceinline__ uint32_t smem_u32(const void* p) {
    uint32_t a;
    asm("{ .reg .u64 t; cvta.to.shared.u64 t, %1; cvt.u32.u64 %0, t; }"
        : "=r"(a) : "l"(p));
    return a;
}
__device__ __forceinline__ float ld_cluster_f32(uint32_t my_addr, uint32_t rank) {
    uint32_t ra; float v;
    asm volatile("mapa.shared::cluster.u32 %0, %1, %2;" : "=r"(ra) : "r"(my_addr), "r"(rank));
    asm volatile("ld.shared::cluster.f32 %0, [%1];" : "=f"(v) : "r"(ra));
    return v;
}
#define CLUSTER_SYNC() do { \
    asm volatile("barrier.cluster.arrive.aligned;" ::: "memory"); \
    asm volatile("barrier.cluster.wait.aligned;"   ::: "memory"); } while (0)

#define THREADS 256
#define TPT     4          // timesteps per thread (two packed pair-streams)
#define KCTA    (THREADS * TPT)   // 1024
#define CSZ     4
#define KSUPER  (KCTA * CSZ)
#define NSWEEP  3
#define NWARP   (THREADS / 32)    // 8

// Parallel-in-time Picard, cluster edition, 4 timesteps/thread, with the
// sweep-0 shortcut: since sweep 0 evaluates the MLP at ys == carry (constant
// in t), U_j = b1_j + W1s^T carry is precomputed once per superblock and the
// whole W1 state contraction disappears from sweep 0's inner loop.
__global__ __launch_bounds__(THREADS, 1) __cluster_dims__(CSZ, 1, 1)
void ode_picard_kernel(const float* __restrict__ x,
                       const float* __restrict__ W1,
                       const float* __restrict__ b1,
                       const float* __restrict__ b2,
                       const float* __restrict__ W2,
                       float* __restrict__ out,
                       int T) {
    extern __shared__ char smx[];
    ull*        w1dup = (ull*)smx;                       // [64][16] (w,w)
    ull*        w2dup = w1dup + 64 * 16;                 // [64][16] (w,w)/sr
    ulonglong2* xbv   = (ulonglong2*)(w2dup + 64 * 16);  // [64] {(w1x,w1x),(b1,b1)}
    ull*        upk   = (ull*)(xbv + 64);                // [64] (U_j, U_j) sweep-0
    ull*        b2dup = upk + 64;                        // [16] (b2/sr, b2/sr)
    float*      A     = (float*)(b2dup + 16);            // [16][KCTA] ys_est
    float*      WT    = A + 16 * KCTA;                   // [8 warps][16]
    float*      carry = WT + NWARP * 16;                 // [16]
    float*      rtot  = carry + 16;                      // [16]
    float*      rbase = rtot + 16;                       // [16]
    float*      cnew  = rbase + 16;                      // [16]

    const int b = blockIdx.x / CSZ;
    uint32_t rank;
    asm("mov.u32 %0, %%cluster_ctarank;" : "=r"(rank));
    const int tid  = threadIdx.x;
    const int lane = tid & 31;
    const int wid  = tid >> 5;
    const float inv_sr = 1.0f / 44100.0f;
    const int nsteps = T - 1;

    // ---- prologue: duplicated-packed weights into smem ----
    if (tid < 64) {
        const int j = tid;
        ulonglong2 xb;
        xb.x = pk2(W1[j], W1[j]);
        xb.y = pk2(b1[j], b1[j]);
        xbv[j] = xb;
        for (int k = 0; k < 16; ++k) {
            const float w1v = W1[(k + 1) * 64 + j];
            w1dup[j * 16 + k] = pk2(w1v, w1v);
            const float w2v = W2[j * 16 + k] * inv_sr;
            w2dup[j * 16 + k] = pk2(w2v, w2v);
        }
    }
    if (tid < 16) {
        const float bv = b2[tid] * inv_sr;
        b2dup[tid] = pk2(bv, bv);
        carry[tid] = 0.0f;
    }
    __syncthreads();

    const uint32_t rtot_addr = smem_u32(rtot + (tid & 15));
    const int nsuper = (nsteps + KSUPER - 1) / KSUPER;
    const int tl = TPT * tid;                // first local step of this thread

    for (int blk = 0; blk < nsuper; ++blk) {
        const int s0 = blk * KSUPER + (int)rank * KCTA + tl;
        const bool v1 = s0 < nsteps,     v2 = s0 + 1 < nsteps;
        const bool v3 = s0 + 2 < nsteps, v4 = s0 + 3 < nsteps;
        const float x1 = v1 ? x[(s0)     * 32 + b] : 0.0f;
        const float x2 = v2 ? x[(s0 + 1) * 32 + b] : 0.0f;
        const float x3 = v3 ? x[(s0 + 2) * 32 + b] : 0.0f;
        const float x4 = v4 ? x[(s0 + 3) * 32 + b] : 0.0f;
        const ull xpA = pk2(x1, x2);
        const ull xpB = pk2(x3, x4);

        // ---- sweep-0 shortcut: U_j = b1_j + W1s^T carry (once/superblock) ----
        if (tid < 64) {
            const int j = tid;
            float u = b1[j];
            const float* w1c = W1 + 64 + j;       // rows 1..16, column j
#pragma unroll
            for (int k = 0; k < 16; ++k)
                u = fmaf(carry[k], w1c[k * 64], u);
            upk[j] = pk2(u, u);
        }

        for (int sw = 0; sw < NSWEEP; ++sw) {
            __syncthreads();   // upk/A/carry/WT visibility

            ull accA[16], accB[16];
#pragma unroll
            for (int m = 0; m < 16; ++m) { accA[m] = b2dup[m]; accB[m] = b2dup[m]; }

            if (sw == 0) {
                // ---- sweep 0: a = U_j + x*w0 (W1 contraction pre-folded) ----
#pragma unroll 4
                for (int j = 0; j < 64; ++j) {
                    const ull w0 = xbv[j].x;
                    const ull u  = upk[j];
                    const ull apA = fma2(xpA, w0, u);
                    const ull apB = fma2(xpB, w0, u);
                    float a1, a2, a3, a4;
                    up2(apA, a1, a2);
                    up2(apB, a3, a4);
                    const ull hpA = pk2(tanh_hw(a1), tanh_hw(a2));
                    const ull hpB = pk2(tanh_hw(a3), tanh_hw(a4));
                    const ulonglong2* w2r =
                        reinterpret_cast<const ulonglong2*>(w2dup + j * 16);
#pragma unroll
                    for (int kk = 0; kk < 8; ++kk) {
                        const ulonglong2 w = w2r[kk];
                        accA[2 * kk]     = fma2(hpA, w.x, accA[2 * kk]);
                        accB[2 * kk]     = fma2(hpB, w.x, accB[2 * kk]);
                        accA[2 * kk + 1] = fma2(hpA, w.y, accA[2 * kk + 1]);
                        accB[2 * kk + 1] = fma2(hpB, w.y, accB[2 * kk + 1]);
                    }
                }
            } else {
                // ---- sweeps 1+: full MLP against refined ys estimates ----
                ull yspA[16], yspB[16];
#pragma unroll
                for (int k = 0; k < 16; ++k) {
                    const float4 f = *reinterpret_cast<const float4*>(A + k * KCTA + tl);
                    yspA[k] = pk2(f.x, f.y);
                    yspB[k] = pk2(f.z, f.w);
                }
#pragma unroll 2
                for (int j = 0; j < 64; ++j) {
                    const ulonglong2 xb = xbv[j];
                    ull apA = fma2(xpA, xb.x, xb.y);
                    ull apB = fma2(xpB, xb.x, xb.y);
                    const ulonglong2* w1r =
                        reinterpret_cast<const ulonglong2*>(w1dup + j * 16);
#pragma unroll
                    for (int kk = 0; kk < 8; ++kk) {
                        const ulonglong2 w = w1r[kk];      // one LDS.128, 4 fma2
                        apA = fma2(yspA[2 * kk],     w.x, apA);
                        apB = fma2(yspB[2 * kk],     w.x, apB);
                        apA = fma2(yspA[2 * kk + 1], w.y, apA);
                        apB = fma2(yspB[2 * kk + 1], w.y, apB);
                    }
                    float a1, a2, a3, a4;
                    up2(apA, a1, a2);
                    up2(apB, a3, a4);
                    const ull hpA = pk2(tanh_hw(a1), tanh_hw(a2));
                    const ull hpB = pk2(tanh_hw(a3), tanh_hw(a4));
                    const ulonglong2* w2r =
                        reinterpret_cast<const ulonglong2*>(w2dup + j * 16);
#pragma unroll
                    for (int kk = 0; kk < 8; ++kk) {
                        const ulonglong2 w = w2r[kk];      // one LDS.128, 4 fma2
                        accA[2 * kk]     = fma2(hpA, w.x, accA[2 * kk]);
                        accB[2 * kk]     = fma2(hpB, w.x, accB[2 * kk]);
                        accA[2 * kk + 1] = fma2(hpA, w.y, accA[2 * kk + 1]);
                        accB[2 * kk + 1] = fma2(hpB, w.y, accB[2 * kk + 1]);
                    }
                }
            }

            // ---- unpack, mask tail, build per-thread cumulative sums ----
            float c1[16], c2[16], c3[16], inc[16], sig[16];
#pragma unroll
            for (int m = 0; m < 16; ++m) {
                float d1, d2, d3, d4;
                up2(accA[m], d1, d2);
                up2(accB[m], d3, d4);
                if (!v1) d1 = 0.0f;
                if (!v2) d2 = 0.0f;
                if (!v3) d3 = 0.0f;
                if (!v4) d4 = 0.0f;
                c1[m]  = d1;
                c2[m]  = d1 + d2;
                c3[m]  = c2[m] + d3;
                sig[m] = c3[m] + d4;
                inc[m] = sig[m];
            }

            // ---- warp inclusive scan of per-thread sums (16 dims) ----
#pragma unroll
            for (int off = 1; off < 32; off <<= 1) {
#pragma unroll
                for (int m = 0; m < 16; ++m) {
                    const float tv = __shfl_up_sync(FULL_MASK, inc[m], off);
                    if (lane >= off) inc[m] += tv;
                }
            }
            if (lane == 31) {
#pragma unroll
                for (int m = 0; m < 16; ++m) WT[wid * 16 + m] = inc[m];
            }
            __syncthreads();

            // ---- this rank's block total -> rtot ----
            if (tid < 16) {
                float s = 0.0f;
                for (int w = 0; w < NWARP; ++w) s += WT[w * 16 + tid];
                rtot[tid] = s;
            }
            CLUSTER_SYNC();

            // ---- cross-rank offsets + next carry ----
            if (tid < 16) {
                float base = carry[tid];
                float all  = 0.0f;
                for (int r = 0; r < CSZ; ++r) {
                    const float v = ld_cluster_f32(rtot_addr, (uint32_t)r);
                    all += v;
                    if (r < (int)rank) base += v;
                }
                rbase[tid] = base;
                cnew[tid]  = carry[tid] + all;
            }
            CLUSTER_SYNC();

            // ---- cross-warp offsets within my CTA ----
            float wofs = 0.0f;
            if (lane < 16) {
                wofs = rbase[lane];
                for (int w = 0; w < wid; ++w) wofs += WT[w * 16 + lane];
            }

            // ---- exclusive states before my four steps ----
            if (sw < NSWEEP - 1) {
#pragma unroll
                for (int m = 0; m < 16; ++m) {
                    const float wo = __shfl_sync(FULL_MASK, wofs, m);
                    const float ex = wo + (inc[m] - sig[m]);
                    float4 f;
                    f.x = ex;
                    f.y = ex + c1[m];
                    f.z = ex + c2[m];
                    f.w = ex + c3[m];
                    *reinterpret_cast<float4*>(A + m * KCTA + tl) = f;
                }
            } else {
                // final sweep: emit trajectory + advance carry replica
                {
                    const float wo = __shfl_sync(FULL_MASK, wofs, 0);
                    const float ex = wo + (inc[0] - sig[0]);
                    if (v1) out[(s0)     * 32 + b] = ex;
                    if (v2) out[(s0 + 1) * 32 + b] = ex + c1[0];
                    if (v3) out[(s0 + 2) * 32 + b] = ex + c2[0];
                    if (v4) out[(s0 + 3) * 32 + b] = ex + c3[0];
                }
                if (tid < 16) carry[tid] = cnew[tid];
                __syncthreads();   // carry final before next superblock's upk
            }
        }
    }

    __syncthreads();
    if (rank == 0 && tid == 0) out[nsteps * 32 + b] = carry[0];  // y_full[T-1]
}

extern "C" void kernel_launch(void* const* d_in, const int* in_sizes, int n_in,
                              void* d_out, int out_size) {
    const float* x  = (const float*)d_in[0];
    const float* W1 = (const float*)d_in[1];
    const float* b1 = (const float*)d_in[2];
    const float* W2 = (const float*)d_in[3];
    const float* b2 = (const float*)d_in[4];
    float* out = (float*)d_out;

    const int T = in_sizes[0] / 32;   // x is (T, B=32, F=1)

    const size_t smem_bytes =
        (64 * 16 + 64 * 16 + 64 + 16) * sizeof(ull) +      // w1dup, w2dup, upk, b2dup
        64 * sizeof(ulonglong2) +                          // xbv
        (16 * KCTA + NWARP * 16 + 16 * 4) * sizeof(float) + 256;
    cudaFuncSetAttribute(ode_picard_kernel,
                         cudaFuncAttributeMaxDynamicSharedMemorySize,
                         (int)smem_bytes);
    ode_picard_kernel<<<32 * CSZ, THREADS, smem_bytes>>>(x, W1, b1, b2, W2, out, T);
}